// round 11
// baseline (speedup 1.0000x reference)
#include <cuda_runtime.h>

#define T_STEPS 1000
#define BATCH   256
#define IN_DIM  3
#define H_DIM   512
#define OUT_DIM 2
#define TAIL    10
#define T_MAIN  (T_STEPS - TAIL)
#define BETA    0.8f
#define THRESH  1.0f

// One block per batch row. 128 threads, each owns 4 consecutive neurons.
// Spikes stored as float4 (STG.128). Readout fused (block covers full H).
__global__ void __launch_bounds__(128, 8)
snn_fused_kernel(const float* __restrict__ x,
                 const float* __restrict__ W1,
                 const float* __restrict__ W2,
                 float* __restrict__ spk_out,
                 float* __restrict__ avg_out)
{
    __shared__ float xs[T_STEPS * IN_DIM];      // 12 KB: this batch row's x trace
    __shared__ float sums[TAIL * OUT_DIM];

    const int b    = blockIdx.x;
    const int tid  = threadIdx.x;
    const int lane = tid & 31;

    // Cooperative load of x_seq[:, b, :]  (x layout [T, B, IN])
    for (int i = tid; i < T_STEPS * IN_DIM; i += 128) {
        int t = i / IN_DIM;
        int c = i - t * IN_DIM;
        xs[i] = x[(t * BATCH + b) * IN_DIM + c];
    }
    if (tid < TAIL * OUT_DIM) sums[tid] = 0.0f;

    const int h = tid * 4;
    // W1 rows for 4 neurons (12 weights)
    float w[4][3];
#pragma unroll
    for (int n = 0; n < 4; ++n) {
        w[n][0] = W1[(h + n) * IN_DIM + 0];
        w[n][1] = W1[(h + n) * IN_DIM + 1];
        w[n][2] = W1[(h + n) * IN_DIM + 2];
    }

    __syncthreads();

    float m[4] = {0.0f, 0.0f, 0.0f, 0.0f};
    float4* op = (float4*)(spk_out + (size_t)b * H_DIM + h);
    const size_t stride4 = (size_t)BATCH * H_DIM / 4;   // float4 units per timestep

    // ---- main scan (no readout) ----
#pragma unroll 8
    for (int t = 0; t < T_MAIN; ++t) {
        const float x0 = xs[3 * t + 0];
        const float x1 = xs[3 * t + 1];
        const float x2 = xs[3 * t + 2];
        float4 s;
        {
            float c0 = fmaf(x2, w[0][2], fmaf(x1, w[0][1], x0 * w[0][0]));
            float n0 = fmaf(BETA, m[0], c0);  n0 = (m[0] > THRESH) ? 0.0f : n0;
            m[0] = n0;  s.x = (n0 > THRESH) ? 1.0f : 0.0f;
        }
        {
            float c1 = fmaf(x2, w[1][2], fmaf(x1, w[1][1], x0 * w[1][0]));
            float n1 = fmaf(BETA, m[1], c1);  n1 = (m[1] > THRESH) ? 0.0f : n1;
            m[1] = n1;  s.y = (n1 > THRESH) ? 1.0f : 0.0f;
        }
        {
            float c2 = fmaf(x2, w[2][2], fmaf(x1, w[2][1], x0 * w[2][0]));
            float n2 = fmaf(BETA, m[2], c2);  n2 = (m[2] > THRESH) ? 0.0f : n2;
            m[2] = n2;  s.z = (n2 > THRESH) ? 1.0f : 0.0f;
        }
        {
            float c3 = fmaf(x2, w[3][2], fmaf(x1, w[3][1], x0 * w[3][0]));
            float n3 = fmaf(BETA, m[3], c3);  n3 = (m[3] > THRESH) ? 0.0f : n3;
            m[3] = n3;  s.w = (n3 > THRESH) ? 1.0f : 0.0f;
        }
        __stcs(&op[(size_t)t * stride4], s);
    }

    // ---- tail: scan + fused readout accumulation ----
    float v2a[4], v2b[4];
#pragma unroll
    for (int n = 0; n < 4; ++n) {
        v2a[n] = W2[h + n];              // o = 0
        v2b[n] = W2[H_DIM + h + n];      // o = 1
    }

    float acc[TAIL][OUT_DIM];
#pragma unroll
    for (int tt = 0; tt < TAIL; ++tt) {
        const int t = T_MAIN + tt;
        const float x0 = xs[3 * t + 0];
        const float x1 = xs[3 * t + 1];
        const float x2 = xs[3 * t + 2];
        float sp[4];
#pragma unroll
        for (int n = 0; n < 4; ++n) {
            float c = fmaf(x2, w[n][2], fmaf(x1, w[n][1], x0 * w[n][0]));
            float nn = fmaf(BETA, m[n], c);  nn = (m[n] > THRESH) ? 0.0f : nn;
            m[n] = nn;  sp[n] = (nn > THRESH) ? 1.0f : 0.0f;
        }
        float4 s4 = make_float4(sp[0], sp[1], sp[2], sp[3]);
        __stcs(&op[(size_t)t * stride4], s4);

        float a0 = sp[0] * v2a[0];
        float a1 = sp[0] * v2b[0];
#pragma unroll
        for (int n = 1; n < 4; ++n) {
            a0 = fmaf(sp[n], v2a[n], a0);
            a1 = fmaf(sp[n], v2b[n], a1);
        }
        acc[tt][0] = a0;
        acc[tt][1] = a1;
    }

    // ---- block reduction over H (4 warps) ----
#pragma unroll
    for (int tt = 0; tt < TAIL; ++tt) {
#pragma unroll
        for (int o = 0; o < OUT_DIM; ++o) {
            float v = acc[tt][o];
            v += __shfl_down_sync(0xFFFFFFFFu, v, 16);
            v += __shfl_down_sync(0xFFFFFFFFu, v, 8);
            v += __shfl_down_sync(0xFFFFFFFFu, v, 4);
            v += __shfl_down_sync(0xFFFFFFFFu, v, 2);
            v += __shfl_down_sync(0xFFFFFFFFu, v, 1);
            if (lane == 0) atomicAdd(&sums[tt * OUT_DIM + o], v);
        }
    }
    __syncthreads();

    if (tid < OUT_DIM) {
        float a = 0.0f;
#pragma unroll
        for (int tt = 0; tt < TAIL; ++tt) {
            const float z = sums[tt * OUT_DIM + tid];
            a += 1.0f / (1.0f + __expf(-z));
        }
        avg_out[b * OUT_DIM + tid] = a * (1.0f / (float)TAIL);
    }
}

extern "C" void kernel_launch(void* const* d_in, const int* in_sizes, int n_in,
                              void* d_out, int out_size)
{
    const float* x  = (const float*)d_in[0];   // [T, B, IN]
    const float* W1 = (const float*)d_in[1];   // [H, IN]
    const float* W2 = (const float*)d_in[2];   // [OUT, H]
    float* out = (float*)d_out;

    float* spk = out;                                          // [T, B, H]
    float* avg = out + (size_t)T_STEPS * BATCH * H_DIM;        // [B, OUT]

    snn_fused_kernel<<<BATCH, 128>>>(x, W1, W2, spk, avg);
}